// round 1
// baseline (speedup 1.0000x reference)
#include <cuda_runtime.h>
#include <cuda_bf16.h>
#include <cstdint>

// Problem constants
#define B 4
#define C 4
#define H 256
#define W 256
#define HW (H*W)          // 65536
#define FS 11
#define PAD 5

// Tile config for attention kernel
#define BW 32             // tile width (output pixels)
#define BH 16             // tile height
#define R  4              // pixels per thread along w
#define NTHREADS 128      // (BW/R) * BH = 8 * 16
#define HALO_W (BW + FS - 1)   // 42
#define HALO_H (BH + FS - 1)   // 26
#define SST 43            // shared row stride in float4 (padded: 43*4 words = 172 ≡ 12 mod 32)

// Scratch: theta (pre-scaled by log2(e)), phi, g in pixel-major float4 layout.
__device__ float4 d_theta[B*HW];
__device__ float4 d_phi[B*HW];
__device__ float4 d_g[B*HW];

__device__ __forceinline__ float ex2(float s) {
    float r;
    asm("ex2.approx.f32 %0, %1;" : "=f"(r) : "f"(s));
    return r;
}

// ---------------------------------------------------------------------------
// Kernel 1: per-pixel 1x1 convs -> theta (scaled by log2 e), phi, g
// ---------------------------------------------------------------------------
__global__ __launch_bounds__(256) void prep_kernel(
    const float* __restrict__ x,
    const float* __restrict__ Wt,
    const float* __restrict__ Wp,
    const float* __restrict__ Wg)
{
    __shared__ float w[48];
    int tid = threadIdx.x;
    if (tid < 16)      w[tid]      = Wt[tid];
    else if (tid < 32) w[tid]      = Wp[tid - 16];
    else if (tid < 48) w[tid]      = Wg[tid - 32];
    __syncthreads();

    int p  = blockIdx.x * 256 + tid;      // 0 .. B*HW-1
    int b  = p >> 16;
    int hw = p & (HW - 1);
    const float* xb = x + b * (C * HW) + hw;
    float x0 = xb[0];
    float x1 = xb[HW];
    float x2 = xb[2*HW];
    float x3 = xb[3*HW];

    const float L2E = 1.4426950408889634f;

    float4 th, ph, gg;
    th.x = fmaf(w[0],  x0, fmaf(w[1],  x1, fmaf(w[2],  x2, w[3]  * x3))) * L2E;
    th.y = fmaf(w[4],  x0, fmaf(w[5],  x1, fmaf(w[6],  x2, w[7]  * x3))) * L2E;
    th.z = fmaf(w[8],  x0, fmaf(w[9],  x1, fmaf(w[10], x2, w[11] * x3))) * L2E;
    th.w = fmaf(w[12], x0, fmaf(w[13], x1, fmaf(w[14], x2, w[15] * x3))) * L2E;

    ph.x = fmaf(w[16], x0, fmaf(w[17], x1, fmaf(w[18], x2, w[19] * x3)));
    ph.y = fmaf(w[20], x0, fmaf(w[21], x1, fmaf(w[22], x2, w[23] * x3)));
    ph.z = fmaf(w[24], x0, fmaf(w[25], x1, fmaf(w[26], x2, w[27] * x3)));
    ph.w = fmaf(w[28], x0, fmaf(w[29], x1, fmaf(w[30], x2, w[31] * x3)));

    gg.x = fmaf(w[32], x0, fmaf(w[33], x1, fmaf(w[34], x2, w[35] * x3)));
    gg.y = fmaf(w[36], x0, fmaf(w[37], x1, fmaf(w[38], x2, w[39] * x3)));
    gg.z = fmaf(w[40], x0, fmaf(w[41], x1, fmaf(w[42], x2, w[43] * x3)));
    gg.w = fmaf(w[44], x0, fmaf(w[45], x1, fmaf(w[46], x2, w[47] * x3)));

    d_theta[p] = th;
    d_phi[p]   = ph;
    d_g[p]     = gg;
}

// ---------------------------------------------------------------------------
// Kernel 2: fused local non-local attention + output conv + residual
// ---------------------------------------------------------------------------
__global__ __launch_bounds__(NTHREADS) void attn_kernel(
    const float* __restrict__ x,
    const float* __restrict__ Ww,
    float* __restrict__ out)
{
    __shared__ float4 phs[HALO_H * SST];
    __shared__ float4 ggs[HALO_H * SST];
    __shared__ float  wws[16];

    int tid = threadIdx.x;
    if (tid < 16) wws[tid] = Ww[tid];

    int b  = blockIdx.z;
    int h0 = blockIdx.y * BH;
    int w0 = blockIdx.x * BW;
    const float4* __restrict__ phg = d_phi + b * HW;
    const float4* __restrict__ ggg = d_g   + b * HW;

    // Cooperative halo load (zero-padded outside image), coalesced along w.
    #pragma unroll
    for (int it = 0; it < (HALO_H * HALO_W + NTHREADS - 1) / NTHREADS; it++) {
        int idx = it * NTHREADS + tid;
        if (idx < HALO_H * HALO_W) {
            int i  = idx / HALO_W;
            int j  = idx - i * HALO_W;
            int gh = h0 - PAD + i;
            int gw = w0 - PAD + j;
            float4 pv = make_float4(0.f, 0.f, 0.f, 0.f);
            float4 gv = make_float4(0.f, 0.f, 0.f, 0.f);
            if ((unsigned)gh < (unsigned)H && (unsigned)gw < (unsigned)W) {
                int g = gh * W + gw;
                pv = phg[g];
                gv = ggg[g];
            }
            phs[i * SST + j] = pv;
            ggs[i * SST + j] = gv;
        }
    }
    __syncthreads();

    // Lane mapping: within a warp ty = lane%4, tx = lane/4 -> conflict-free
    // LDS.128 phases given SST=43 (172 words/row, 12 mod 32 bank skew).
    int tx = (tid >> 2) & 7;
    int ty = ((tid >> 5) << 2) | (tid & 3);
    int oh = h0 + ty;
    int ow = w0 + tx * R;

    float4 th[R];
    float4 acc[R];
    float  sum[R];
    const float4* __restrict__ thg = d_theta + b * HW;
    #pragma unroll
    for (int r = 0; r < R; r++) {
        th[r]  = thg[oh * W + ow + r];
        acc[r] = make_float4(0.f, 0.f, 0.f, 0.f);
        sum[r] = 0.f;
    }

    int base = ty * SST + tx * R;   // shared-f4 index of (local row ty, local col tx*R)

    for (int ki = 0; ki < FS; ki++) {
        const float4* prow = &phs[base + ki * SST];
        const float4* grow = &ggs[base + ki * SST];
        float4 p[FS - 1 + R];
        float4 g[FS - 1 + R];
        #pragma unroll
        for (int j = 0; j < FS - 1 + R; j++) {
            p[j] = prow[j];
            g[j] = grow[j];
        }
        #pragma unroll
        for (int kj = 0; kj < FS; kj++) {
            #pragma unroll
            for (int r = 0; r < R; r++) {
                float4 ph = p[kj + r];
                float s = th[r].x * ph.x;
                s = fmaf(th[r].y, ph.y, s);
                s = fmaf(th[r].z, ph.z, s);
                s = fmaf(th[r].w, ph.w, s);
                float e = ex2(s);      // theta pre-scaled by log2(e)
                sum[r] += e;
                float4 gv = g[kj + r];
                acc[r].x = fmaf(e, gv.x, acc[r].x);
                acc[r].y = fmaf(e, gv.y, acc[r].y);
                acc[r].z = fmaf(e, gv.z, acc[r].z);
                acc[r].w = fmaf(e, gv.w, acc[r].w);
            }
        }
    }

    // Epilogue: normalize, 1x1 conv with Ww, residual, store (plane layout).
    const float* xb = x + b * (C * HW);
    float* ob = out + b * (C * HW);
    #pragma unroll
    for (int r = 0; r < R; r++) {
        float inv = __frcp_rn(sum[r]);
        float ox = acc[r].x * inv;
        float oy = acc[r].y * inv;
        float oz = acc[r].z * inv;
        float owv = acc[r].w * inv;
        int pix = oh * W + ow + r;
        #pragma unroll
        for (int c = 0; c < C; c++) {
            float res = fmaf(wws[c*4+0], ox,
                        fmaf(wws[c*4+1], oy,
                        fmaf(wws[c*4+2], oz,
                             wws[c*4+3] * owv)));
            ob[c * HW + pix] = res + xb[c * HW + pix];
        }
    }
}

// ---------------------------------------------------------------------------
extern "C" void kernel_launch(void* const* d_in, const int* in_sizes, int n_in,
                              void* d_out, int out_size)
{
    const float* x  = (const float*)d_in[0];
    const float* Wt = (const float*)d_in[1];
    const float* Wp = (const float*)d_in[2];
    const float* Wg = (const float*)d_in[3];
    const float* Ww = (const float*)d_in[4];
    float* out = (float*)d_out;

    prep_kernel<<<(B * HW) / 256, 256>>>(x, Wt, Wp, Wg);

    dim3 grid(W / BW, H / BH, B);
    attn_kernel<<<grid, NTHREADS>>>(x, Ww, out);
}